// round 10
// baseline (speedup 1.0000x reference)
#include <cuda_runtime.h>
#include <cuda_fp16.h>
#include <cstdint>

// Problem constants (match reference)
#define NN   100000
#define DD   128
#define HH   8
#define CC   16
#define EE   800000
#define ETOT 900000          // E + N self-loops
#define NEG_SLOPE 0.2f
#define ALPHA_BASE (NN * DD + 2 * ETOT)

// scan config
#define SCAN_T   512
#define SCAN_IT  4
#define SCAN_PB  (SCAN_T * SCAN_IT)              // 2048
#define SCAN_NB  ((NN + SCAN_PB - 1) / SCAN_PB)  // 49

// Scratch (static __device__ globals; allocation is forbidden)
__device__ __align__(16) __half g_hh[NN * DD];   // projected features (fp16) 25.6 MB
__device__ __align__(16) float g_as [NN * HH];   // a_src (fp32, from MMA accum)
__device__ __align__(16) float g_ad [NN * HH];   // a_dst
__device__ int g_cnt [NN];
__device__ int g_inc [NN];
__device__ int g_bsum[SCAN_NB];
__device__ int g_off [NN + 1];
__device__ int g_cur [NN];
__device__ int g_esrc[ETOT];
__device__ int g_eid [ETOT];

// ===========================================================================
// tf32 mma.sync GEMM:  h = x @ W  with 3-pass tf32 split, fused att epilogue
// ===========================================================================
#define LDA 132
#define GEMM_SMEM_BYTES ((2 * 128 * LDA + 256) * 4)

__device__ __forceinline__ uint32_t f2tf32(float f) {
    uint32_t r;
    asm("cvt.rna.tf32.f32 %0, %1;" : "=r"(r) : "f"(f));
    return r;
}
__device__ __forceinline__ void mma_tf32(float* c,
                                         uint32_t a0, uint32_t a1, uint32_t a2, uint32_t a3,
                                         uint32_t b0, uint32_t b1) {
    asm volatile("mma.sync.aligned.m16n8k8.row.col.f32.tf32.tf32.f32 "
                 "{%0,%1,%2,%3}, {%4,%5,%6,%7}, {%8,%9}, {%0,%1,%2,%3};"
                 : "+f"(c[0]), "+f"(c[1]), "+f"(c[2]), "+f"(c[3])
                 : "r"(a0), "r"(a1), "r"(a2), "r"(a3), "r"(b0), "r"(b1));
}

__global__ __launch_bounds__(256, 1)
void k_gemm_tc(const float* __restrict__ x, const float* __restrict__ W,
               const float* __restrict__ att_src, const float* __restrict__ att_dst) {
    extern __shared__ float smf[];
    float* As   = smf;                    // [128][LDA]
    float* Bs   = smf + 128 * LDA;        // [128][LDA]  (W transposed)
    float* Satt = smf + 2 * 128 * LDA;

    const int tid  = threadIdx.x;
    const int wid  = tid >> 5;
    const int lane = tid & 31;
    const int gid  = lane >> 2;
    const int tig  = lane & 3;
    const int bm   = blockIdx.x * 128;
    const int wr   = wid & 1;
    const int wc   = wid >> 1;
    const int mbase = wr * 64;
    const int nbase = wc * 32;

    #pragma unroll
    for (int i = 0; i < 16; i++) {
        int f = tid + i * 256;
        int row = f >> 5, c4 = f & 31;
        float4 v = make_float4(0.f, 0.f, 0.f, 0.f);
        if (bm + row < NN) v = *(const float4*)&x[(size_t)(bm + row) * DD + c4 * 4];
        float* p = &As[row * LDA + c4 * 4];
        p[0] = v.x; p[1] = v.y; p[2] = v.z; p[3] = v.w;
    }
    #pragma unroll
    for (int i = 0; i < 16; i++) {
        int f = tid + i * 256;
        int k = f >> 5, n4 = f & 31;
        float4 v = *(const float4*)&W[(size_t)k * DD + n4 * 4];
        Bs[(n4 * 4 + 0) * LDA + k] = v.x;
        Bs[(n4 * 4 + 1) * LDA + k] = v.y;
        Bs[(n4 * 4 + 2) * LDA + k] = v.z;
        Bs[(n4 * 4 + 3) * LDA + k] = v.w;
    }
    if (tid < 128) {
        Satt[tid]       = att_src[tid];
        Satt[128 + tid] = att_dst[tid];
    }
    __syncthreads();

    float acc[4][4][4];
    #pragma unroll
    for (int mt = 0; mt < 4; mt++)
        #pragma unroll
        for (int nt = 0; nt < 4; nt++)
            #pragma unroll
            for (int j = 0; j < 4; j++) acc[mt][nt][j] = 0.f;

    #pragma unroll 2
    for (int kt = 0; kt < 16; kt++) {
        const int kc = kt * 8 + tig;
        uint32_t ah[4][4], al[4][4];
        #pragma unroll
        for (int mt = 0; mt < 4; mt++) {
            int r0 = (mbase + mt * 16 + gid) * LDA;
            int r1 = r0 + 8 * LDA;
            float a0 = As[r0 + kc], a1 = As[r1 + kc];
            float a2 = As[r0 + kc + 4], a3 = As[r1 + kc + 4];
            ah[mt][0] = f2tf32(a0); al[mt][0] = f2tf32(a0 - __uint_as_float(ah[mt][0]));
            ah[mt][1] = f2tf32(a1); al[mt][1] = f2tf32(a1 - __uint_as_float(ah[mt][1]));
            ah[mt][2] = f2tf32(a2); al[mt][2] = f2tf32(a2 - __uint_as_float(ah[mt][2]));
            ah[mt][3] = f2tf32(a3); al[mt][3] = f2tf32(a3 - __uint_as_float(ah[mt][3]));
        }
        uint32_t bh[4][2], bl[4][2];
        #pragma unroll
        for (int nt = 0; nt < 4; nt++) {
            int nr = (nbase + nt * 8 + gid) * LDA;
            float b0 = Bs[nr + kc], b1 = Bs[nr + kc + 4];
            bh[nt][0] = f2tf32(b0); bl[nt][0] = f2tf32(b0 - __uint_as_float(bh[nt][0]));
            bh[nt][1] = f2tf32(b1); bl[nt][1] = f2tf32(b1 - __uint_as_float(bh[nt][1]));
        }
        #pragma unroll
        for (int mt = 0; mt < 4; mt++)
            #pragma unroll
            for (int nt = 0; nt < 4; nt++) {
                mma_tf32(acc[mt][nt], ah[mt][0], ah[mt][1], ah[mt][2], ah[mt][3],
                         bh[nt][0], bh[nt][1]);
                mma_tf32(acc[mt][nt], ah[mt][0], ah[mt][1], ah[mt][2], ah[mt][3],
                         bl[nt][0], bl[nt][1]);
                mma_tf32(acc[mt][nt], al[mt][0], al[mt][1], al[mt][2], al[mt][3],
                         bh[nt][0], bh[nt][1]);
            }
    }

    #pragma unroll
    for (int mt = 0; mt < 4; mt++) {
        #pragma unroll
        for (int half = 0; half < 2; half++) {
            const int grow = bm + mbase + mt * 16 + half * 8 + gid;
            const bool ok  = (grow < NN);
            float sacc[2] = {0.f, 0.f}, dacc[2] = {0.f, 0.f};
            #pragma unroll
            for (int nt = 0; nt < 4; nt++) {
                float v0 = acc[mt][nt][half * 2];
                float v1 = acc[mt][nt][half * 2 + 1];
                int c0 = nbase + nt * 8 + tig * 2;
                if (ok) {
                    *(__half2*)&g_hh[(size_t)grow * DD + c0] = __floats2half2_rn(v0, v1);
                }
                int hl = nt >> 1;
                sacc[hl] = fmaf(v0, Satt[c0], fmaf(v1, Satt[c0 + 1], sacc[hl]));
                dacc[hl] = fmaf(v0, Satt[128 + c0], fmaf(v1, Satt[128 + c0 + 1], dacc[hl]));
            }
            #pragma unroll
            for (int o = 1; o <= 2; o <<= 1) {
                #pragma unroll
                for (int hl = 0; hl < 2; hl++) {
                    sacc[hl] += __shfl_xor_sync(0xffffffffu, sacc[hl], o);
                    dacc[hl] += __shfl_xor_sync(0xffffffffu, dacc[hl], o);
                }
            }
            if (ok && tig == 0) {
                #pragma unroll
                for (int hl = 0; hl < 2; hl++) {
                    g_as[grow * HH + wc * 2 + hl] = sacc[hl];
                    g_ad[grow * HH + wc * 2 + hl] = dacc[hl];
                }
            }
        }
    }
}

// ---------------------------------------------------------------------------
// CSR build
// ---------------------------------------------------------------------------
__global__ void k_init_cnt() {
    int i = blockIdx.x * blockDim.x + threadIdx.x;
    if (i < NN) g_cnt[i] = 1;
}

__global__ void k_hist(const int* __restrict__ ei) {
    int e = blockIdx.x * blockDim.x + threadIdx.x;
    if (e < EE) atomicAdd(&g_cnt[ei[EE + e]], 1);
}

__global__ void k_scan_blocks() {
    __shared__ int ssum[SCAN_T];
    int b = blockIdx.x, t = threadIdx.x;
    int base = b * SCAN_PB + t * SCAN_IT;
    int v[SCAN_IT];
    int tot = 0;
    #pragma unroll
    for (int k = 0; k < SCAN_IT; k++) {
        v[k] = (base + k < NN) ? g_cnt[base + k] : 0;
        tot += v[k];
    }
    ssum[t] = tot;
    __syncthreads();
    for (int o = 1; o < SCAN_T; o <<= 1) {
        int x = (t >= o) ? ssum[t - o] : 0;
        __syncthreads();
        ssum[t] += x;
        __syncthreads();
    }
    int run = ssum[t] - tot;
    #pragma unroll
    for (int k = 0; k < SCAN_IT; k++) {
        run += v[k];
        if (base + k < NN) g_inc[base + k] = run;
    }
    if (t == SCAN_T - 1) g_bsum[b] = ssum[SCAN_T - 1];
}

// fused top-level scan + offset apply (49 block sums in smem per block)
__global__ void k_scan_add() {
    __shared__ int sb[SCAN_NB];
    int t = threadIdx.x;
    if (t < SCAN_NB) sb[t] = g_bsum[t];
    __syncthreads();
    int i = blockIdx.x * blockDim.x + t;
    if (i >= NN) return;
    int mb = i / SCAN_PB;
    int ex = 0;
    for (int j = 0; j < mb; j++) ex += sb[j];
    int excl = g_inc[i] - g_cnt[i] + ex;
    g_off[i] = excl;
    g_cur[i] = excl;
    if (i == 0) g_off[NN] = ETOT;
}

__global__ void k_scatter(const int* __restrict__ ei, float* __restrict__ out, int full) {
    int e = blockIdx.x * blockDim.x + threadIdx.x;
    if (e >= ETOT) return;
    int s, d;
    if (e < EE) { s = ei[e]; d = ei[EE + e]; }
    else        { s = e - EE; d = s; }
    int pos = atomicAdd(&g_cur[d], 1);
    g_esrc[pos] = s;
    g_eid[pos]  = e;
    if (full) {
        out[NN * DD + e]        = (float)s;
        out[NN * DD + ETOT + e] = (float)d;
    }
}

// ---------------------------------------------------------------------------
// fused softmax + aggregation: one warp per destination node
// fast path (deg <= 32): single gather of g_as, alpha cached in smem
// messages gathered from fp16 g_hh (half the L2 traffic of fp32)
// ---------------------------------------------------------------------------
__global__ __launch_bounds__(256)
void k_aggregate(float* __restrict__ out, const float* __restrict__ bias, int full) {
    __shared__ float s_alpha[8][32][8];
    __shared__ int   s_src  [8][32];

    const int warp = (blockIdx.x * blockDim.x + threadIdx.x) >> 5;
    const int lane = threadIdx.x & 31;
    const int w    = threadIdx.x >> 5;
    if (warp >= NN) return;
    const int n   = warp;
    const int beg = g_off[n];
    const int deg = g_off[n + 1] - beg;
    const int hd  = lane >> 2;
    const int q   = lane & 3;

    float4 ad0 = *(const float4*)&g_ad[n * HH];
    float4 ad1 = *(const float4*)&g_ad[n * HH + 4];
    const float adv[8] = { ad0.x, ad0.y, ad0.z, ad0.w, ad1.x, ad1.y, ad1.z, ad1.w };

    if (deg <= 32) {
        // ---- fast path: lane j owns edge j ----
        float l[8];
        int   s = 0, eid = 0;
        if (lane < deg) {
            s   = g_esrc[beg + lane];
            eid = g_eid[beg + lane];
            float4 s0 = *(const float4*)&g_as[s * HH];
            float4 s1 = *(const float4*)&g_as[s * HH + 4];
            float t[8] = { s0.x + adv[0], s0.y + adv[1], s0.z + adv[2], s0.w + adv[3],
                           s1.x + adv[4], s1.y + adv[5], s1.z + adv[6], s1.w + adv[7] };
            #pragma unroll
            for (int r = 0; r < 8; r++) l[r] = (t[r] > 0.f) ? t[r] : NEG_SLOPE * t[r];
        } else {
            #pragma unroll
            for (int r = 0; r < 8; r++) l[r] = __int_as_float(0xFF800000);
        }
        float mx[8];
        #pragma unroll
        for (int r = 0; r < 8; r++) mx[r] = l[r];
        #pragma unroll
        for (int o = 16; o > 0; o >>= 1)
            #pragma unroll
            for (int r = 0; r < 8; r++)
                mx[r] = fmaxf(mx[r], __shfl_xor_sync(0xffffffffu, mx[r], o));

        float ex[8], den[8];
        #pragma unroll
        for (int r = 0; r < 8; r++) {
            ex[r]  = (lane < deg) ? __expf(l[r] - mx[r]) : 0.f;
            den[r] = ex[r];
        }
        #pragma unroll
        for (int o = 16; o > 0; o >>= 1)
            #pragma unroll
            for (int r = 0; r < 8; r++)
                den[r] += __shfl_xor_sync(0xffffffffu, den[r], o);

        float al[8];
        #pragma unroll
        for (int r = 0; r < 8; r++) al[r] = ex[r] / (den[r] + 1e-16f);

        if (lane < deg) {
            s_src[w][lane] = s;
            #pragma unroll
            for (int r = 0; r < 8; r++) s_alpha[w][lane][r] = al[r];
            if (full) {
                float* ap = &out[ALPHA_BASE + (size_t)eid * HH];
                *(float4*)ap       = make_float4(al[0], al[1], al[2], al[3]);
                *(float4*)(ap + 4) = make_float4(al[4], al[5], al[6], al[7]);
            }
        }
        __syncwarp();

        float4 acc = make_float4(0.f, 0.f, 0.f, 0.f);
        for (int j = 0; j < deg; j++) {
            int   sj    = s_src[w][j];
            float alpha = s_alpha[w][j][hd];
            uint2 raw = *(const uint2*)&g_hh[(size_t)sj * DD + hd * CC + q * 4];
            float2 f0 = __half22float2(*(__half2*)&raw.x);
            float2 f1 = __half22float2(*(__half2*)&raw.y);
            acc.x = fmaf(alpha, f0.x, acc.x);
            acc.y = fmaf(alpha, f0.y, acc.y);
            acc.z = fmaf(alpha, f1.x, acc.z);
            acc.w = fmaf(alpha, f1.y, acc.w);
        }
        float4 b = *(const float4*)&bias[lane * 4];
        acc.x += b.x; acc.y += b.y; acc.z += b.z; acc.w += b.w;
        *(float4*)&out[(size_t)n * DD + lane * 4] = acc;
        return;
    }

    // ---- fallback: deg > 32 (rare) ----
    float mx[8];
    #pragma unroll
    for (int r = 0; r < 8; r++) mx[r] = __int_as_float(0xFF800000);
    for (int j = lane; j < deg; j += 32) {
        int s = g_esrc[beg + j];
        float4 s0 = *(const float4*)&g_as[s * HH];
        float4 s1 = *(const float4*)&g_as[s * HH + 4];
        float l[8] = { s0.x + adv[0], s0.y + adv[1], s0.z + adv[2], s0.w + adv[3],
                       s1.x + adv[4], s1.y + adv[5], s1.z + adv[6], s1.w + adv[7] };
        #pragma unroll
        for (int r = 0; r < 8; r++) {
            float v = (l[r] > 0.f) ? l[r] : NEG_SLOPE * l[r];
            mx[r] = fmaxf(mx[r], v);
        }
    }
    #pragma unroll
    for (int o = 16; o > 0; o >>= 1)
        #pragma unroll
        for (int r = 0; r < 8; r++)
            mx[r] = fmaxf(mx[r], __shfl_xor_sync(0xffffffffu, mx[r], o));

    float den[8];
    #pragma unroll
    for (int r = 0; r < 8; r++) den[r] = 0.f;
    for (int j = lane; j < deg; j += 32) {
        int s = g_esrc[beg + j];
        float4 s0 = *(const float4*)&g_as[s * HH];
        float4 s1 = *(const float4*)&g_as[s * HH + 4];
        float l[8] = { s0.x + adv[0], s0.y + adv[1], s0.z + adv[2], s0.w + adv[3],
                       s1.x + adv[4], s1.y + adv[5], s1.z + adv[6], s1.w + adv[7] };
        #pragma unroll
        for (int r = 0; r < 8; r++) {
            float v = (l[r] > 0.f) ? l[r] : NEG_SLOPE * l[r];
            den[r] += __expf(v - mx[r]);
        }
    }
    #pragma unroll
    for (int o = 16; o > 0; o >>= 1)
        #pragma unroll
        for (int r = 0; r < 8; r++)
            den[r] += __shfl_xor_sync(0xffffffffu, den[r], o);

    if (lane < 8) { s_alpha[w][0][lane] = mx[lane]; s_alpha[w][1][lane] = den[lane]; }
    __syncwarp();
    const float m_h   = s_alpha[w][0][hd];
    const float den_h = s_alpha[w][1][hd] + 1e-16f;
    const float adh   = adv[hd];

    float4 acc = make_float4(0.f, 0.f, 0.f, 0.f);
    for (int j = 0; j < deg; j++) {
        int s = g_esrc[beg + j];
        float l = g_as[s * HH + hd] + adh;
        l = (l > 0.f) ? l : NEG_SLOPE * l;
        float alpha = __expf(l - m_h) / den_h;
        if (full && q == 0) {
            int eid = g_eid[beg + j];
            out[ALPHA_BASE + (size_t)eid * HH + hd] = alpha;
        }
        uint2 raw = *(const uint2*)&g_hh[(size_t)s * DD + hd * CC + q * 4];
        float2 f0 = __half22float2(*(__half2*)&raw.x);
        float2 f1 = __half22float2(*(__half2*)&raw.y);
        acc.x = fmaf(alpha, f0.x, acc.x);
        acc.y = fmaf(alpha, f0.y, acc.y);
        acc.z = fmaf(alpha, f1.x, acc.z);
        acc.w = fmaf(alpha, f1.y, acc.w);
    }
    float4 b = *(const float4*)&bias[lane * 4];
    acc.x += b.x; acc.y += b.y; acc.z += b.z; acc.w += b.w;
    *(float4*)&out[(size_t)n * DD + lane * 4] = acc;
}

// ---------------------------------------------------------------------------
extern "C" void kernel_launch(void* const* d_in, const int* in_sizes, int n_in,
                              void* d_out, int out_size) {
    const float* x       = (const float*)d_in[0];
    const int*   ei      = (const int*)d_in[1];    // int32 (JAX x64 disabled)
    const float* W       = (const float*)d_in[2];
    const float* att_src = (const float*)d_in[3];
    const float* att_dst = (const float*)d_in[4];
    const float* bias    = (const float*)d_in[5];
    float* out = (float*)d_out;

    const int full = (out_size > NN * DD) ? 1 : 0;

    cudaFuncSetAttribute(k_gemm_tc, cudaFuncAttributeMaxDynamicSharedMemorySize,
                         GEMM_SMEM_BYTES);

    // fork-join: CSR build (side stream) overlaps the GEMM (main stream)
    cudaStream_t s2;
    cudaEvent_t evFork, evJoin;
    bool forked = (cudaStreamCreateWithFlags(&s2, cudaStreamNonBlocking) == cudaSuccess);
    if (forked) {
        cudaEventCreateWithFlags(&evFork, cudaEventDisableTiming);
        cudaEventCreateWithFlags(&evJoin, cudaEventDisableTiming);
    }

    if (forked) {
        cudaEventRecord(evFork, 0);
        cudaStreamWaitEvent(s2, evFork, 0);
        k_init_cnt<<<(NN + 255) / 256, 256, 0, s2>>>();
        k_hist<<<(EE + 255) / 256, 256, 0, s2>>>(ei);
        k_scan_blocks<<<SCAN_NB, SCAN_T, 0, s2>>>();
        k_scan_add<<<(NN + 255) / 256, 256, 0, s2>>>();
        k_scatter<<<(ETOT + 255) / 256, 256, 0, s2>>>(ei, out, full);
        cudaEventRecord(evJoin, s2);

        k_gemm_tc<<<(NN + 127) / 128, 256, GEMM_SMEM_BYTES>>>(x, W, att_src, att_dst);
        cudaStreamWaitEvent(0, evJoin, 0);
    } else {
        k_init_cnt<<<(NN + 255) / 256, 256>>>();
        k_hist<<<(EE + 255) / 256, 256>>>(ei);
        k_scan_blocks<<<SCAN_NB, SCAN_T>>>();
        k_scan_add<<<(NN + 255) / 256, 256>>>();
        k_scatter<<<(ETOT + 255) / 256, 256>>>(ei, out, full);
        k_gemm_tc<<<(NN + 127) / 128, 256, GEMM_SMEM_BYTES>>>(x, W, att_src, att_dst);
    }

    long long tc = (long long)NN * 32;
    k_aggregate<<<(int)((tc + 255) / 256), 256>>>(out, bias, full);

    if (forked) {
        cudaEventDestroy(evFork);
        cudaEventDestroy(evJoin);
        cudaStreamDestroy(s2);
    }
}

// round 11
// speedup vs baseline: 1.4150x; 1.4150x over previous
#include <cuda_runtime.h>
#include <cuda_fp16.h>
#include <cstdint>

// Problem constants (match reference)
#define NN   100000
#define DD   128
#define HH   8
#define CC   16
#define EE   800000
#define ETOT 900000          // E + N self-loops
#define NEG_SLOPE 0.2f
#define ALPHA_BASE (NN * DD + 2 * ETOT)

// scan config
#define SCAN_T   512
#define SCAN_IT  4
#define SCAN_PB  (SCAN_T * SCAN_IT)              // 2048
#define SCAN_NB  ((NN + SCAN_PB - 1) / SCAN_PB)  // 49

// Scratch (static __device__ globals; allocation is forbidden)
__device__ __align__(16) float g_h  [NN * DD];   // projected features (fp32)
__device__ __align__(16) float g_as [NN * HH];   // a_src
__device__ __align__(16) float g_ad [NN * HH];   // a_dst
__device__ int g_cnt [NN];
__device__ int g_inc [NN];
__device__ int g_bsum[SCAN_NB];
__device__ int g_bex [SCAN_NB];
__device__ int g_off [NN + 1];
__device__ int g_cur [NN];
__device__ int g_esrc[ETOT];
__device__ int g_eid [ETOT];

// ===========================================================================
// tf32 mma.sync GEMM:  h = x @ W  with 3-pass tf32 split, fused att epilogue
// ===========================================================================
#define LDA 132
#define GEMM_SMEM_BYTES ((2 * 128 * LDA + 256) * 4)

__device__ __forceinline__ uint32_t f2tf32(float f) {
    uint32_t r;
    asm("cvt.rna.tf32.f32 %0, %1;" : "=r"(r) : "f"(f));
    return r;
}
__device__ __forceinline__ void mma_tf32(float* c,
                                         uint32_t a0, uint32_t a1, uint32_t a2, uint32_t a3,
                                         uint32_t b0, uint32_t b1) {
    asm volatile("mma.sync.aligned.m16n8k8.row.col.f32.tf32.tf32.f32 "
                 "{%0,%1,%2,%3}, {%4,%5,%6,%7}, {%8,%9}, {%0,%1,%2,%3};"
                 : "+f"(c[0]), "+f"(c[1]), "+f"(c[2]), "+f"(c[3])
                 : "r"(a0), "r"(a1), "r"(a2), "r"(a3), "r"(b0), "r"(b1));
}

__global__ __launch_bounds__(256, 1)
void k_gemm_tc(const float* __restrict__ x, const float* __restrict__ W,
               const float* __restrict__ att_src, const float* __restrict__ att_dst) {
    extern __shared__ float smf[];
    float* As   = smf;                    // [128][LDA]
    float* Bs   = smf + 128 * LDA;        // [128][LDA]  (W transposed)
    float* Satt = smf + 2 * 128 * LDA;

    const int tid  = threadIdx.x;
    const int wid  = tid >> 5;
    const int lane = tid & 31;
    const int gid  = lane >> 2;
    const int tig  = lane & 3;
    const int bm   = blockIdx.x * 128;
    const int wr   = wid & 1;
    const int wc   = wid >> 1;
    const int mbase = wr * 64;
    const int nbase = wc * 32;

    #pragma unroll
    for (int i = 0; i < 16; i++) {
        int f = tid + i * 256;
        int row = f >> 5, c4 = f & 31;
        float4 v = make_float4(0.f, 0.f, 0.f, 0.f);
        if (bm + row < NN) v = *(const float4*)&x[(size_t)(bm + row) * DD + c4 * 4];
        float* p = &As[row * LDA + c4 * 4];
        p[0] = v.x; p[1] = v.y; p[2] = v.z; p[3] = v.w;
    }
    #pragma unroll
    for (int i = 0; i < 16; i++) {
        int f = tid + i * 256;
        int k = f >> 5, n4 = f & 31;
        float4 v = *(const float4*)&W[(size_t)k * DD + n4 * 4];
        Bs[(n4 * 4 + 0) * LDA + k] = v.x;
        Bs[(n4 * 4 + 1) * LDA + k] = v.y;
        Bs[(n4 * 4 + 2) * LDA + k] = v.z;
        Bs[(n4 * 4 + 3) * LDA + k] = v.w;
    }
    if (tid < 128) {
        Satt[tid]       = att_src[tid];
        Satt[128 + tid] = att_dst[tid];
    }
    __syncthreads();

    float acc[4][4][4];
    #pragma unroll
    for (int mt = 0; mt < 4; mt++)
        #pragma unroll
        for (int nt = 0; nt < 4; nt++)
            #pragma unroll
            for (int j = 0; j < 4; j++) acc[mt][nt][j] = 0.f;

    #pragma unroll 2
    for (int kt = 0; kt < 16; kt++) {
        const int kc = kt * 8 + tig;
        uint32_t ah[4][4], al[4][4];
        #pragma unroll
        for (int mt = 0; mt < 4; mt++) {
            int r0 = (mbase + mt * 16 + gid) * LDA;
            int r1 = r0 + 8 * LDA;
            float a0 = As[r0 + kc], a1 = As[r1 + kc];
            float a2 = As[r0 + kc + 4], a3 = As[r1 + kc + 4];
            ah[mt][0] = f2tf32(a0); al[mt][0] = f2tf32(a0 - __uint_as_float(ah[mt][0]));
            ah[mt][1] = f2tf32(a1); al[mt][1] = f2tf32(a1 - __uint_as_float(ah[mt][1]));
            ah[mt][2] = f2tf32(a2); al[mt][2] = f2tf32(a2 - __uint_as_float(ah[mt][2]));
            ah[mt][3] = f2tf32(a3); al[mt][3] = f2tf32(a3 - __uint_as_float(ah[mt][3]));
        }
        uint32_t bh[4][2], bl[4][2];
        #pragma unroll
        for (int nt = 0; nt < 4; nt++) {
            int nr = (nbase + nt * 8 + gid) * LDA;
            float b0 = Bs[nr + kc], b1 = Bs[nr + kc + 4];
            bh[nt][0] = f2tf32(b0); bl[nt][0] = f2tf32(b0 - __uint_as_float(bh[nt][0]));
            bh[nt][1] = f2tf32(b1); bl[nt][1] = f2tf32(b1 - __uint_as_float(bh[nt][1]));
        }
        #pragma unroll
        for (int mt = 0; mt < 4; mt++)
            #pragma unroll
            for (int nt = 0; nt < 4; nt++) {
                mma_tf32(acc[mt][nt], ah[mt][0], ah[mt][1], ah[mt][2], ah[mt][3],
                         bh[nt][0], bh[nt][1]);
                mma_tf32(acc[mt][nt], ah[mt][0], ah[mt][1], ah[mt][2], ah[mt][3],
                         bl[nt][0], bl[nt][1]);
                mma_tf32(acc[mt][nt], al[mt][0], al[mt][1], al[mt][2], al[mt][3],
                         bh[nt][0], bh[nt][1]);
            }
    }

    #pragma unroll
    for (int mt = 0; mt < 4; mt++) {
        #pragma unroll
        for (int half = 0; half < 2; half++) {
            const int grow = bm + mbase + mt * 16 + half * 8 + gid;
            const bool ok  = (grow < NN);
            float sacc[2] = {0.f, 0.f}, dacc[2] = {0.f, 0.f};
            #pragma unroll
            for (int nt = 0; nt < 4; nt++) {
                float v0 = acc[mt][nt][half * 2];
                float v1 = acc[mt][nt][half * 2 + 1];
                int c0 = nbase + nt * 8 + tig * 2;
                if (ok) {
                    float2 st = make_float2(v0, v1);
                    *(float2*)&g_h[(size_t)grow * DD + c0] = st;
                }
                int hl = nt >> 1;
                sacc[hl] = fmaf(v0, Satt[c0], fmaf(v1, Satt[c0 + 1], sacc[hl]));
                dacc[hl] = fmaf(v0, Satt[128 + c0], fmaf(v1, Satt[128 + c0 + 1], dacc[hl]));
            }
            #pragma unroll
            for (int o = 1; o <= 2; o <<= 1) {
                #pragma unroll
                for (int hl = 0; hl < 2; hl++) {
                    sacc[hl] += __shfl_xor_sync(0xffffffffu, sacc[hl], o);
                    dacc[hl] += __shfl_xor_sync(0xffffffffu, dacc[hl], o);
                }
            }
            if (ok && tig == 0) {
                #pragma unroll
                for (int hl = 0; hl < 2; hl++) {
                    g_as[grow * HH + wc * 2 + hl] = sacc[hl];
                    g_ad[grow * HH + wc * 2 + hl] = dacc[hl];
                }
            }
        }
    }
}

// ---------------------------------------------------------------------------
// CSR build
// ---------------------------------------------------------------------------
__global__ void k_init_cnt() {
    int i = blockIdx.x * blockDim.x + threadIdx.x;
    if (i < NN) g_cnt[i] = 1;
}

__global__ void k_hist(const int* __restrict__ ei) {
    int e = blockIdx.x * blockDim.x + threadIdx.x;
    if (e < EE) atomicAdd(&g_cnt[ei[EE + e]], 1);
}

__global__ void k_scan_blocks() {
    __shared__ int ssum[SCAN_T];
    int b = blockIdx.x, t = threadIdx.x;
    int base = b * SCAN_PB + t * SCAN_IT;
    int v[SCAN_IT];
    int tot = 0;
    #pragma unroll
    for (int k = 0; k < SCAN_IT; k++) {
        v[k] = (base + k < NN) ? g_cnt[base + k] : 0;
        tot += v[k];
    }
    ssum[t] = tot;
    __syncthreads();
    for (int o = 1; o < SCAN_T; o <<= 1) {
        int x = (t >= o) ? ssum[t - o] : 0;
        __syncthreads();
        ssum[t] += x;
        __syncthreads();
    }
    int run = ssum[t] - tot;
    #pragma unroll
    for (int k = 0; k < SCAN_IT; k++) {
        run += v[k];
        if (base + k < NN) g_inc[base + k] = run;
    }
    if (t == SCAN_T - 1) g_bsum[b] = ssum[SCAN_T - 1];
}

__global__ void k_scan_top() {   // warp-parallel scan over SCAN_NB (<=64) blocks
    int lane = threadIdx.x;
    int a  = (lane < SCAN_NB) ? g_bsum[lane] : 0;
    int a0 = a;
    #pragma unroll
    for (int o = 1; o < 32; o <<= 1) { int t = __shfl_up_sync(~0u, a, o); if (lane >= o) a += t; }
    int tot = __shfl_sync(~0u, a, 31);
    int bb  = (lane + 32 < SCAN_NB) ? g_bsum[lane + 32] : 0;
    int b0  = bb;
    #pragma unroll
    for (int o = 1; o < 32; o <<= 1) { int t = __shfl_up_sync(~0u, bb, o); if (lane >= o) bb += t; }
    if (lane < SCAN_NB)      g_bex[lane]      = a - a0;
    if (lane + 32 < SCAN_NB) g_bex[lane + 32] = tot + bb - b0;
}

__global__ void k_scan_add() {
    int i = blockIdx.x * blockDim.x + threadIdx.x;
    if (i >= NN) return;
    int excl = g_inc[i] - g_cnt[i] + g_bex[i / SCAN_PB];
    g_off[i] = excl;
    g_cur[i] = excl;
    if (i == 0) g_off[NN] = ETOT;
}

// CSR scatter only (ei->out writes moved to k_write_ei on the main stream)
__global__ void k_scatter(const int* __restrict__ ei) {
    int e = blockIdx.x * blockDim.x + threadIdx.x;
    if (e >= ETOT) return;
    int s, d;
    if (e < EE) { s = ei[e]; d = ei[EE + e]; }
    else        { s = e - EE; d = s; }
    int pos = atomicAdd(&g_cur[d], 1);
    g_esrc[pos] = s;
    g_eid[pos]  = e;
}

__global__ void k_write_ei(const int* __restrict__ ei, float* __restrict__ out) {
    int e = blockIdx.x * blockDim.x + threadIdx.x;
    if (e >= ETOT) return;
    int s, d;
    if (e < EE) { s = ei[e]; d = ei[EE + e]; }
    else        { s = e - EE; d = s; }
    out[NN * DD + e]        = (float)s;
    out[NN * DD + ETOT + e] = (float)d;
}

// ---------------------------------------------------------------------------
// fused softmax + aggregation: one warp per destination node
// fast path (deg <= 32): single gather of g_as, alpha cached in smem
// ---------------------------------------------------------------------------
__global__ __launch_bounds__(256)
void k_aggregate(float* __restrict__ out, const float* __restrict__ bias, int full) {
    __shared__ float s_alpha[8][32][8];
    __shared__ int   s_src  [8][32];

    const int warp = (blockIdx.x * blockDim.x + threadIdx.x) >> 5;
    const int lane = threadIdx.x & 31;
    const int w    = threadIdx.x >> 5;
    if (warp >= NN) return;
    const int n   = warp;
    const int beg = g_off[n];
    const int deg = g_off[n + 1] - beg;
    const int hd  = lane >> 2;
    const int q   = lane & 3;

    float4 ad0 = *(const float4*)&g_ad[n * HH];
    float4 ad1 = *(const float4*)&g_ad[n * HH + 4];
    const float adv[8] = { ad0.x, ad0.y, ad0.z, ad0.w, ad1.x, ad1.y, ad1.z, ad1.w };

    if (deg <= 32) {
        // ---- fast path: lane j owns edge j ----
        float l[8];
        int   s = 0, eid = 0;
        if (lane < deg) {
            s   = g_esrc[beg + lane];
            eid = g_eid[beg + lane];
            float4 s0 = *(const float4*)&g_as[s * HH];
            float4 s1 = *(const float4*)&g_as[s * HH + 4];
            float t[8] = { s0.x + adv[0], s0.y + adv[1], s0.z + adv[2], s0.w + adv[3],
                           s1.x + adv[4], s1.y + adv[5], s1.z + adv[6], s1.w + adv[7] };
            #pragma unroll
            for (int r = 0; r < 8; r++) l[r] = (t[r] > 0.f) ? t[r] : NEG_SLOPE * t[r];
        } else {
            #pragma unroll
            for (int r = 0; r < 8; r++) l[r] = __int_as_float(0xFF800000);
        }
        float mx[8];
        #pragma unroll
        for (int r = 0; r < 8; r++) mx[r] = l[r];
        #pragma unroll
        for (int o = 16; o > 0; o >>= 1)
            #pragma unroll
            for (int r = 0; r < 8; r++)
                mx[r] = fmaxf(mx[r], __shfl_xor_sync(0xffffffffu, mx[r], o));

        float ex[8], den[8];
        #pragma unroll
        for (int r = 0; r < 8; r++) {
            ex[r]  = (lane < deg) ? __expf(l[r] - mx[r]) : 0.f;
            den[r] = ex[r];
        }
        #pragma unroll
        for (int o = 16; o > 0; o >>= 1)
            #pragma unroll
            for (int r = 0; r < 8; r++)
                den[r] += __shfl_xor_sync(0xffffffffu, den[r], o);

        float al[8];
        #pragma unroll
        for (int r = 0; r < 8; r++) al[r] = ex[r] / (den[r] + 1e-16f);

        if (lane < deg) {
            s_src[w][lane] = s;
            #pragma unroll
            for (int r = 0; r < 8; r++) s_alpha[w][lane][r] = al[r];
            if (full) {
                float* ap = &out[ALPHA_BASE + (size_t)eid * HH];
                *(float4*)ap       = make_float4(al[0], al[1], al[2], al[3]);
                *(float4*)(ap + 4) = make_float4(al[4], al[5], al[6], al[7]);
            }
        }
        __syncwarp();

        // phase C: channel-parallel over lanes, unrolled over edges for MLP
        float4 acc = make_float4(0.f, 0.f, 0.f, 0.f);
        #pragma unroll 4
        for (int j = 0; j < deg; j++) {
            int   sj    = s_src[w][j];
            float alpha = s_alpha[w][j][hd];
            float4 hv = __ldg((const float4*)&g_h[(size_t)sj * DD + hd * CC + q * 4]);
            acc.x = fmaf(alpha, hv.x, acc.x);
            acc.y = fmaf(alpha, hv.y, acc.y);
            acc.z = fmaf(alpha, hv.z, acc.z);
            acc.w = fmaf(alpha, hv.w, acc.w);
        }
        float4 b = *(const float4*)&bias[lane * 4];
        acc.x += b.x; acc.y += b.y; acc.z += b.z; acc.w += b.w;
        *(float4*)&out[(size_t)n * DD + lane * 4] = acc;
        return;
    }

    // ---- fallback: deg > 32 (rare) ----
    float mx[8];
    #pragma unroll
    for (int r = 0; r < 8; r++) mx[r] = __int_as_float(0xFF800000);
    for (int j = lane; j < deg; j += 32) {
        int s = g_esrc[beg + j];
        float4 s0 = *(const float4*)&g_as[s * HH];
        float4 s1 = *(const float4*)&g_as[s * HH + 4];
        float l[8] = { s0.x + adv[0], s0.y + adv[1], s0.z + adv[2], s0.w + adv[3],
                       s1.x + adv[4], s1.y + adv[5], s1.z + adv[6], s1.w + adv[7] };
        #pragma unroll
        for (int r = 0; r < 8; r++) {
            float v = (l[r] > 0.f) ? l[r] : NEG_SLOPE * l[r];
            mx[r] = fmaxf(mx[r], v);
        }
    }
    #pragma unroll
    for (int o = 16; o > 0; o >>= 1)
        #pragma unroll
        for (int r = 0; r < 8; r++)
            mx[r] = fmaxf(mx[r], __shfl_xor_sync(0xffffffffu, mx[r], o));

    float den[8];
    #pragma unroll
    for (int r = 0; r < 8; r++) den[r] = 0.f;
    for (int j = lane; j < deg; j += 32) {
        int s = g_esrc[beg + j];
        float4 s0 = *(const float4*)&g_as[s * HH];
        float4 s1 = *(const float4*)&g_as[s * HH + 4];
        float l[8] = { s0.x + adv[0], s0.y + adv[1], s0.z + adv[2], s0.w + adv[3],
                       s1.x + adv[4], s1.y + adv[5], s1.z + adv[6], s1.w + adv[7] };
        #pragma unroll
        for (int r = 0; r < 8; r++) {
            float v = (l[r] > 0.f) ? l[r] : NEG_SLOPE * l[r];
            den[r] += __expf(v - mx[r]);
        }
    }
    #pragma unroll
    for (int o = 16; o > 0; o >>= 1)
        #pragma unroll
        for (int r = 0; r < 8; r++)
            den[r] += __shfl_xor_sync(0xffffffffu, den[r], o);

    if (lane < 8) { s_alpha[w][0][lane] = mx[lane]; s_alpha[w][1][lane] = den[lane]; }
    __syncwarp();
    const float m_h   = s_alpha[w][0][hd];
    const float den_h = s_alpha[w][1][hd] + 1e-16f;
    const float adh   = adv[hd];

    float4 acc = make_float4(0.f, 0.f, 0.f, 0.f);
    for (int j = 0; j < deg; j++) {
        int s = g_esrc[beg + j];
        float l = g_as[s * HH + hd] + adh;
        l = (l > 0.f) ? l : NEG_SLOPE * l;
        float alpha = __expf(l - m_h) / den_h;
        if (full && q == 0) {
            int eid = g_eid[beg + j];
            out[ALPHA_BASE + (size_t)eid * HH + hd] = alpha;
        }
        float4 hv = __ldg((const float4*)&g_h[(size_t)s * DD + hd * CC + q * 4]);
        acc.x = fmaf(alpha, hv.x, acc.x);
        acc.y = fmaf(alpha, hv.y, acc.y);
        acc.z = fmaf(alpha, hv.z, acc.z);
        acc.w = fmaf(alpha, hv.w, acc.w);
    }
    float4 b = *(const float4*)&bias[lane * 4];
    acc.x += b.x; acc.y += b.y; acc.z += b.z; acc.w += b.w;
    *(float4*)&out[(size_t)n * DD + lane * 4] = acc;
}

// ---------------------------------------------------------------------------
extern "C" void kernel_launch(void* const* d_in, const int* in_sizes, int n_in,
                              void* d_out, int out_size) {
    const float* x       = (const float*)d_in[0];
    const int*   ei      = (const int*)d_in[1];    // int32 (JAX x64 disabled)
    const float* W       = (const float*)d_in[2];
    const float* att_src = (const float*)d_in[3];
    const float* att_dst = (const float*)d_in[4];
    const float* bias    = (const float*)d_in[5];
    float* out = (float*)d_out;

    const int full = (out_size > NN * DD) ? 1 : 0;

    cudaFuncSetAttribute(k_gemm_tc, cudaFuncAttributeMaxDynamicSharedMemorySize,
                         GEMM_SMEM_BYTES);

    // fork-join: CSR build (side stream) overlaps the GEMM + ei-writes (main)
    cudaStream_t s2;
    cudaEvent_t evFork, evJoin;
    bool forked = (cudaStreamCreateWithFlags(&s2, cudaStreamNonBlocking) == cudaSuccess);
    if (forked) {
        cudaEventCreateWithFlags(&evFork, cudaEventDisableTiming);
        cudaEventCreateWithFlags(&evJoin, cudaEventDisableTiming);
    }

    if (forked) {
        cudaEventRecord(evFork, 0);
        cudaStreamWaitEvent(s2, evFork, 0);
        k_init_cnt<<<(NN + 255) / 256, 256, 0, s2>>>();
        k_hist<<<(EE + 255) / 256, 256, 0, s2>>>(ei);
        k_scan_blocks<<<SCAN_NB, SCAN_T, 0, s2>>>();
        k_scan_top<<<1, 32, 0, s2>>>();
        k_scan_add<<<(NN + 255) / 256, 256, 0, s2>>>();
        k_scatter<<<(ETOT + 255) / 256, 256, 0, s2>>>(ei);
        cudaEventRecord(evJoin, s2);

        k_gemm_tc<<<(NN + 127) / 128, 256, GEMM_SMEM_BYTES>>>(x, W, att_src, att_dst);
        if (full) k_write_ei<<<(ETOT + 255) / 256, 256>>>(ei, out);
        cudaStreamWaitEvent(0, evJoin, 0);
    } else {
        k_init_cnt<<<(NN + 255) / 256, 256>>>();
        k_hist<<<(EE + 255) / 256, 256>>>(ei);
        k_scan_blocks<<<SCAN_NB, SCAN_T>>>();
        k_scan_top<<<1, 32>>>();
        k_scan_add<<<(NN + 255) / 256, 256>>>();
        k_scatter<<<(ETOT + 255) / 256, 256>>>(ei);
        k_gemm_tc<<<(NN + 127) / 128, 256, GEMM_SMEM_BYTES>>>(x, W, att_src, att_dst);
        if (full) k_write_ei<<<(ETOT + 255) / 256, 256>>>(ei, out);
    }

    long long tc = (long long)NN * 32;
    k_aggregate<<<(int)((tc + 255) / 256), 256>>>(out, bias, full);

    if (forked) {
        cudaEventDestroy(evFork);
        cudaEventDestroy(evJoin);
        cudaStreamDestroy(s2);
    }
}

// round 12
// speedup vs baseline: 1.4160x; 1.0007x over previous
#include <cuda_runtime.h>
#include <cuda_fp16.h>
#include <cstdint>

// Problem constants (match reference)
#define NN   100000
#define DD   128
#define HH   8
#define CC   16
#define EE   800000
#define ETOT 900000          // E + N self-loops
#define NEG_SLOPE 0.2f
#define ALPHA_BASE (NN * DD + 2 * ETOT)

// scan config
#define SCAN_T   512
#define SCAN_IT  4
#define SCAN_PB  (SCAN_T * SCAN_IT)              // 2048
#define SCAN_NB  ((NN + SCAN_PB - 1) / SCAN_PB)  // 49

// Scratch (static __device__ globals; allocation is forbidden)
__device__ __align__(16) float g_h  [NN * DD];   // projected features (fp32)
__device__ __align__(16) float g_as [NN * HH];   // a_src
__device__ __align__(16) float g_ad [NN * HH];   // a_dst
__device__ int g_cnt [NN];
__device__ int g_inc [NN];
__device__ int g_bsum[SCAN_NB];
__device__ int g_off [NN + 1];
__device__ int g_cur [NN];
__device__ int g_esrc[ETOT];
__device__ int g_eid [ETOT];

// ===========================================================================
// fp16-split mma.sync GEMM:  h = x @ W  (hi*hi + hi*lo + lo*hi), fused att
// smem: 4 half tiles [128][LDH] (A_hi, A_lo, B_hi, B_lo) + att vectors.
// Conversion to fp16 done ONCE at tile load; inner loop is LDS + MMA only.
// ===========================================================================
#define LDH 136                                    // halfs per row (pad: conflict-free)
#define TILE_H (128 * LDH)                         // halfs per tile
#define GEMM_SMEM_BYTES (4 * TILE_H * 2 + 256 * 4)

__device__ __forceinline__ void mma_f16(float* c, uint32_t a0, uint32_t a1,
                                        uint32_t a2, uint32_t a3,
                                        uint32_t b0, uint32_t b1) {
    asm volatile("mma.sync.aligned.m16n8k16.row.col.f32.f16.f16.f32 "
                 "{%0,%1,%2,%3}, {%4,%5,%6,%7}, {%8,%9}, {%0,%1,%2,%3};"
                 : "+f"(c[0]), "+f"(c[1]), "+f"(c[2]), "+f"(c[3])
                 : "r"(a0), "r"(a1), "r"(a2), "r"(a3), "r"(b0), "r"(b1));
}

__global__ __launch_bounds__(256, 1)
void k_gemm_tc(const float* __restrict__ x, const float* __restrict__ W,
               const float* __restrict__ att_src, const float* __restrict__ att_dst) {
    extern __shared__ char smraw[];
    __half* As_hi = (__half*)smraw;
    __half* As_lo = As_hi + TILE_H;
    __half* Bs_hi = As_lo + TILE_H;
    __half* Bs_lo = Bs_hi + TILE_H;
    float*  Satt  = (float*)(Bs_lo + TILE_H);      // [0:128]=att_src, [128:256]=att_dst

    const int tid  = threadIdx.x;
    const int wid  = tid >> 5;
    const int lane = tid & 31;
    const int gid  = lane >> 2;
    const int tig  = lane & 3;
    const int bm   = blockIdx.x * 128;
    const int wr   = wid & 1;
    const int wc   = wid >> 1;
    const int mbase = wr * 64;
    const int nbase = wc * 32;

    // load + split x tile [128 rows][128 cols]
    #pragma unroll
    for (int i = 0; i < 16; i++) {
        int f = tid + i * 256;
        int row = f >> 5, c4 = f & 31;
        float4 v = make_float4(0.f, 0.f, 0.f, 0.f);
        if (bm + row < NN) v = *(const float4*)&x[(size_t)(bm + row) * DD + c4 * 4];
        float vv[4] = { v.x, v.y, v.z, v.w };
        #pragma unroll
        for (int j = 0; j < 4; j++) {
            __half hi = __float2half_rn(vv[j]);
            __half lo = __float2half_rn(vv[j] - __half2float(hi));
            As_hi[row * LDH + c4 * 4 + j] = hi;
            As_lo[row * LDH + c4 * 4 + j] = lo;
        }
    }
    // load + split + transpose W -> Bs[n][k]
    #pragma unroll
    for (int i = 0; i < 16; i++) {
        int f = tid + i * 256;
        int k = f >> 5, n4 = f & 31;
        float4 v = *(const float4*)&W[(size_t)k * DD + n4 * 4];
        float vv[4] = { v.x, v.y, v.z, v.w };
        #pragma unroll
        for (int j = 0; j < 4; j++) {
            __half hi = __float2half_rn(vv[j]);
            __half lo = __float2half_rn(vv[j] - __half2float(hi));
            Bs_hi[(n4 * 4 + j) * LDH + k] = hi;
            Bs_lo[(n4 * 4 + j) * LDH + k] = lo;
        }
    }
    if (tid < 128) {
        Satt[tid]       = att_src[tid];
        Satt[128 + tid] = att_dst[tid];
    }
    __syncthreads();

    float acc[4][4][4];
    #pragma unroll
    for (int mt = 0; mt < 4; mt++)
        #pragma unroll
        for (int nt = 0; nt < 4; nt++)
            #pragma unroll
            for (int j = 0; j < 4; j++) acc[mt][nt][j] = 0.f;

    #pragma unroll
    for (int kt = 0; kt < 8; kt++) {
        const int kc = kt * 16 + tig * 2;
        uint32_t ah[4][4], al[4][4];
        #pragma unroll
        for (int mt = 0; mt < 4; mt++) {
            int r0 = (mbase + mt * 16 + gid) * LDH;
            int r1 = r0 + 8 * LDH;
            ah[mt][0] = *(const uint32_t*)&As_hi[r0 + kc];
            ah[mt][1] = *(const uint32_t*)&As_hi[r1 + kc];
            ah[mt][2] = *(const uint32_t*)&As_hi[r0 + kc + 8];
            ah[mt][3] = *(const uint32_t*)&As_hi[r1 + kc + 8];
            al[mt][0] = *(const uint32_t*)&As_lo[r0 + kc];
            al[mt][1] = *(const uint32_t*)&As_lo[r1 + kc];
            al[mt][2] = *(const uint32_t*)&As_lo[r0 + kc + 8];
            al[mt][3] = *(const uint32_t*)&As_lo[r1 + kc + 8];
        }
        uint32_t bh[4][2], bl[4][2];
        #pragma unroll
        for (int nt = 0; nt < 4; nt++) {
            int nr = (nbase + nt * 8 + gid) * LDH;
            bh[nt][0] = *(const uint32_t*)&Bs_hi[nr + kc];
            bh[nt][1] = *(const uint32_t*)&Bs_hi[nr + kc + 8];
            bl[nt][0] = *(const uint32_t*)&Bs_lo[nr + kc];
            bl[nt][1] = *(const uint32_t*)&Bs_lo[nr + kc + 8];
        }
        #pragma unroll
        for (int mt = 0; mt < 4; mt++)
            #pragma unroll
            for (int nt = 0; nt < 4; nt++) {
                mma_f16(acc[mt][nt], ah[mt][0], ah[mt][1], ah[mt][2], ah[mt][3],
                        bh[nt][0], bh[nt][1]);
                mma_f16(acc[mt][nt], ah[mt][0], ah[mt][1], ah[mt][2], ah[mt][3],
                        bl[nt][0], bl[nt][1]);
                mma_f16(acc[mt][nt], al[mt][0], al[mt][1], al[mt][2], al[mt][3],
                        bh[nt][0], bh[nt][1]);
            }
    }

    // epilogue: store h rows (fp32) + fused per-head att dots
    #pragma unroll
    for (int mt = 0; mt < 4; mt++) {
        #pragma unroll
        for (int half = 0; half < 2; half++) {
            const int grow = bm + mbase + mt * 16 + half * 8 + gid;
            const bool ok  = (grow < NN);
            float sacc[2] = {0.f, 0.f}, dacc[2] = {0.f, 0.f};
            #pragma unroll
            for (int nt = 0; nt < 4; nt++) {
                float v0 = acc[mt][nt][half * 2];
                float v1 = acc[mt][nt][half * 2 + 1];
                int c0 = nbase + nt * 8 + tig * 2;
                if (ok) {
                    float2 st = make_float2(v0, v1);
                    *(float2*)&g_h[(size_t)grow * DD + c0] = st;
                }
                int hl = nt >> 1;
                sacc[hl] = fmaf(v0, Satt[c0], fmaf(v1, Satt[c0 + 1], sacc[hl]));
                dacc[hl] = fmaf(v0, Satt[128 + c0], fmaf(v1, Satt[128 + c0 + 1], dacc[hl]));
            }
            #pragma unroll
            for (int o = 1; o <= 2; o <<= 1) {
                #pragma unroll
                for (int hl = 0; hl < 2; hl++) {
                    sacc[hl] += __shfl_xor_sync(0xffffffffu, sacc[hl], o);
                    dacc[hl] += __shfl_xor_sync(0xffffffffu, dacc[hl], o);
                }
            }
            if (ok && tig == 0) {
                #pragma unroll
                for (int hl = 0; hl < 2; hl++) {
                    g_as[grow * HH + wc * 2 + hl] = sacc[hl];
                    g_ad[grow * HH + wc * 2 + hl] = dacc[hl];
                }
            }
        }
    }
}

// ---------------------------------------------------------------------------
// CSR build  (g_cnt memset to 0 host-side; self-loop +1 folded into the scan)
// ---------------------------------------------------------------------------
__global__ void k_hist(const int* __restrict__ ei) {
    int e = blockIdx.x * blockDim.x + threadIdx.x;
    if (e < EE) atomicAdd(&g_cnt[ei[EE + e]], 1);
}

__global__ void k_scan_blocks() {
    __shared__ int ssum[SCAN_T];
    int b = blockIdx.x, t = threadIdx.x;
    int base = b * SCAN_PB + t * SCAN_IT;
    int v[SCAN_IT];
    int tot = 0;
    #pragma unroll
    for (int k = 0; k < SCAN_IT; k++) {
        v[k] = (base + k < NN) ? (g_cnt[base + k] + 1) : 0;   // +1 self-loop
        tot += v[k];
    }
    ssum[t] = tot;
    __syncthreads();
    for (int o = 1; o < SCAN_T; o <<= 1) {
        int x = (t >= o) ? ssum[t - o] : 0;
        __syncthreads();
        ssum[t] += x;
        __syncthreads();
    }
    int run = ssum[t] - tot;
    #pragma unroll
    for (int k = 0; k < SCAN_IT; k++) {
        run += v[k];
        if (base + k < NN) g_inc[base + k] = run;
    }
    if (t == SCAN_T - 1) g_bsum[b] = ssum[SCAN_T - 1];
}

// fused top-level scan + offset apply (49 block sums in smem)
__global__ void k_scan_add() {
    __shared__ int sb[SCAN_NB];
    int t = threadIdx.x;
    if (t < SCAN_NB) sb[t] = g_bsum[t];
    __syncthreads();
    int i = blockIdx.x * blockDim.x + t;
    if (i >= NN) return;
    int mb = i / SCAN_PB;
    int ex = 0;
    for (int j = 0; j < mb; j++) ex += sb[j];
    int excl = g_inc[i] - (g_cnt[i] + 1) + ex;
    g_off[i] = excl;
    g_cur[i] = excl;
    if (i == 0) g_off[NN] = ETOT;
}

// CSR scatter only (ei->out writes live on the main stream)
__global__ void k_scatter(const int* __restrict__ ei) {
    int e = blockIdx.x * blockDim.x + threadIdx.x;
    if (e >= ETOT) return;
    int s, d;
    if (e < EE) { s = ei[e]; d = ei[EE + e]; }
    else        { s = e - EE; d = s; }
    int pos = atomicAdd(&g_cur[d], 1);
    g_esrc[pos] = s;
    g_eid[pos]  = e;
}

__global__ void k_write_ei(const int* __restrict__ ei, float* __restrict__ out) {
    int e = blockIdx.x * blockDim.x + threadIdx.x;
    if (e >= ETOT) return;
    int s, d;
    if (e < EE) { s = ei[e]; d = ei[EE + e]; }
    else        { s = e - EE; d = s; }
    out[NN * DD + e]        = (float)s;
    out[NN * DD + ETOT + e] = (float)d;
}

// ---------------------------------------------------------------------------
// fused softmax + aggregation: one warp per destination node
// ---------------------------------------------------------------------------
__global__ __launch_bounds__(256)
void k_aggregate(float* __restrict__ out, const float* __restrict__ bias, int full) {
    __shared__ float s_alpha[8][32][8];
    __shared__ int   s_src  [8][32];

    const int warp = (blockIdx.x * blockDim.x + threadIdx.x) >> 5;
    const int lane = threadIdx.x & 31;
    const int w    = threadIdx.x >> 5;
    if (warp >= NN) return;
    const int n   = warp;
    const int beg = g_off[n];
    const int deg = g_off[n + 1] - beg;
    const int hd  = lane >> 2;
    const int q   = lane & 3;

    float4 ad0 = *(const float4*)&g_ad[n * HH];
    float4 ad1 = *(const float4*)&g_ad[n * HH + 4];
    const float adv[8] = { ad0.x, ad0.y, ad0.z, ad0.w, ad1.x, ad1.y, ad1.z, ad1.w };

    if (deg <= 32) {
        float l[8];
        int   s = 0, eid = 0;
        if (lane < deg) {
            s   = g_esrc[beg + lane];
            eid = g_eid[beg + lane];
            float4 s0 = *(const float4*)&g_as[s * HH];
            float4 s1 = *(const float4*)&g_as[s * HH + 4];
            float t[8] = { s0.x + adv[0], s0.y + adv[1], s0.z + adv[2], s0.w + adv[3],
                           s1.x + adv[4], s1.y + adv[5], s1.z + adv[6], s1.w + adv[7] };
            #pragma unroll
            for (int r = 0; r < 8; r++) l[r] = (t[r] > 0.f) ? t[r] : NEG_SLOPE * t[r];
        } else {
            #pragma unroll
            for (int r = 0; r < 8; r++) l[r] = __int_as_float(0xFF800000);
        }
        float mx[8];
        #pragma unroll
        for (int r = 0; r < 8; r++) mx[r] = l[r];
        #pragma unroll
        for (int o = 16; o > 0; o >>= 1)
            #pragma unroll
            for (int r = 0; r < 8; r++)
                mx[r] = fmaxf(mx[r], __shfl_xor_sync(0xffffffffu, mx[r], o));

        float ex[8], den[8];
        #pragma unroll
        for (int r = 0; r < 8; r++) {
            ex[r]  = (lane < deg) ? __expf(l[r] - mx[r]) : 0.f;
            den[r] = ex[r];
        }
        #pragma unroll
        for (int o = 16; o > 0; o >>= 1)
            #pragma unroll
            for (int r = 0; r < 8; r++)
                den[r] += __shfl_xor_sync(0xffffffffu, den[r], o);

        float al[8];
        #pragma unroll
        for (int r = 0; r < 8; r++) al[r] = ex[r] / (den[r] + 1e-16f);

        if (lane < deg) {
            s_src[w][lane] = s;
            #pragma unroll
            for (int r = 0; r < 8; r++) s_alpha[w][lane][r] = al[r];
            if (full) {
                float* ap = &out[ALPHA_BASE + (size_t)eid * HH];
                *(float4*)ap       = make_float4(al[0], al[1], al[2], al[3]);
                *(float4*)(ap + 4) = make_float4(al[4], al[5], al[6], al[7]);
            }
        }
        __syncwarp();

        float4 acc = make_float4(0.f, 0.f, 0.f, 0.f);
        #pragma unroll 4
        for (int j = 0; j < deg; j++) {
            int   sj    = s_src[w][j];
            float alpha = s_alpha[w][j][hd];
            float4 hv = __ldg((const float4*)&g_h[(size_t)sj * DD + hd * CC + q * 4]);
            acc.x = fmaf(alpha, hv.x, acc.x);
            acc.y = fmaf(alpha, hv.y, acc.y);
            acc.z = fmaf(alpha, hv.z, acc.z);
            acc.w = fmaf(alpha, hv.w, acc.w);
        }
        float4 b = *(const float4*)&bias[lane * 4];
        acc.x += b.x; acc.y += b.y; acc.z += b.z; acc.w += b.w;
        *(float4*)&out[(size_t)n * DD + lane * 4] = acc;
        return;
    }

    // fallback: deg > 32
    float mx[8];
    #pragma unroll
    for (int r = 0; r < 8; r++) mx[r] = __int_as_float(0xFF800000);
    for (int j = lane; j < deg; j += 32) {
        int s = g_esrc[beg + j];
        float4 s0 = *(const float4*)&g_as[s * HH];
        float4 s1 = *(const float4*)&g_as[s * HH + 4];
        float l[8] = { s0.x + adv[0], s0.y + adv[1], s0.z + adv[2], s0.w + adv[3],
                       s1.x + adv[4], s1.y + adv[5], s1.z + adv[6], s1.w + adv[7] };
        #pragma unroll
        for (int r = 0; r < 8; r++) {
            float v = (l[r] > 0.f) ? l[r] : NEG_SLOPE * l[r];
            mx[r] = fmaxf(mx[r], v);
        }
    }
    #pragma unroll
    for (int o = 16; o > 0; o >>= 1)
        #pragma unroll
        for (int r = 0; r < 8; r++)
            mx[r] = fmaxf(mx[r], __shfl_xor_sync(0xffffffffu, mx[r], o));

    float den[8];
    #pragma unroll
    for (int r = 0; r < 8; r++) den[r] = 0.f;
    for (int j = lane; j < deg; j += 32) {
        int s = g_esrc[beg + j];
        float4 s0 = *(const float4*)&g_as[s * HH];
        float4 s1 = *(const float4*)&g_as[s * HH + 4];
        float l[8] = { s0.x + adv[0], s0.y + adv[1], s0.z + adv[2], s0.w + adv[3],
                       s1.x + adv[4], s1.y + adv[5], s1.z + adv[6], s1.w + adv[7] };
        #pragma unroll
        for (int r = 0; r < 8; r++) {
            float v = (l[r] > 0.f) ? l[r] : NEG_SLOPE * l[r];
            den[r] += __expf(v - mx[r]);
        }
    }
    #pragma unroll
    for (int o = 16; o > 0; o >>= 1)
        #pragma unroll
        for (int r = 0; r < 8; r++)
            den[r] += __shfl_xor_sync(0xffffffffu, den[r], o);

    if (lane < 8) { s_alpha[w][0][lane] = mx[lane]; s_alpha[w][1][lane] = den[lane]; }
    __syncwarp();
    const float m_h   = s_alpha[w][0][hd];
    const float den_h = s_alpha[w][1][hd] + 1e-16f;
    const float adh   = adv[hd];

    float4 acc = make_float4(0.f, 0.f, 0.f, 0.f);
    for (int j = 0; j < deg; j++) {
        int s = g_esrc[beg + j];
        float l = g_as[s * HH + hd] + adh;
        l = (l > 0.f) ? l : NEG_SLOPE * l;
        float alpha = __expf(l - m_h) / den_h;
        if (full && q == 0) {
            int eid = g_eid[beg + j];
            out[ALPHA_BASE + (size_t)eid * HH + hd] = alpha;
        }
        float4 hv = __ldg((const float4*)&g_h[(size_t)s * DD + hd * CC + q * 4]);
        acc.x = fmaf(alpha, hv.x, acc.x);
        acc.y = fmaf(alpha, hv.y, acc.y);
        acc.z = fmaf(alpha, hv.z, acc.z);
        acc.w = fmaf(alpha, hv.w, acc.w);
    }
    float4 b = *(const float4*)&bias[lane * 4];
    acc.x += b.x; acc.y += b.y; acc.z += b.z; acc.w += b.w;
    *(float4*)&out[(size_t)n * DD + lane * 4] = acc;
}

// ---------------------------------------------------------------------------
extern "C" void kernel_launch(void* const* d_in, const int* in_sizes, int n_in,
                              void* d_out, int out_size) {
    const float* x       = (const float*)d_in[0];
    const int*   ei      = (const int*)d_in[1];    // int32 (JAX x64 disabled)
    const float* W       = (const float*)d_in[2];
    const float* att_src = (const float*)d_in[3];
    const float* att_dst = (const float*)d_in[4];
    const float* bias    = (const float*)d_in[5];
    float* out = (float*)d_out;

    const int full = (out_size > NN * DD) ? 1 : 0;

    cudaFuncSetAttribute(k_gemm_tc, cudaFuncAttributeMaxDynamicSharedMemorySize,
                         GEMM_SMEM_BYTES);

    void* cnt_ptr = nullptr;
    cudaGetSymbolAddress(&cnt_ptr, g_cnt);

    // fork-join: CSR build (side stream) overlaps GEMM + ei-writes (main)
    cudaStream_t s2;
    cudaEvent_t evFork, evJoin;
    bool forked = (cudaStreamCreateWithFlags(&s2, cudaStreamNonBlocking) == cudaSuccess);
    if (forked) {
        cudaEventCreateWithFlags(&evFork, cudaEventDisableTiming);
        cudaEventCreateWithFlags(&evJoin, cudaEventDisableTiming);
    }

    if (forked) {
        cudaEventRecord(evFork, 0);
        cudaStreamWaitEvent(s2, evFork, 0);
        cudaMemsetAsync(cnt_ptr, 0, NN * sizeof(int), s2);
        k_hist<<<(EE + 255) / 256, 256, 0, s2>>>(ei);
        k_scan_blocks<<<SCAN_NB, SCAN_T, 0, s2>>>();
        k_scan_add<<<(NN + 255) / 256, 256, 0, s2>>>();
        k_scatter<<<(ETOT + 255) / 256, 256, 0, s2>>>(ei);
        cudaEventRecord(evJoin, s2);

        k_gemm_tc<<<(NN + 127) / 128, 256, GEMM_SMEM_BYTES>>>(x, W, att_src, att_dst);
        if (full) k_write_ei<<<(ETOT + 255) / 256, 256>>>(ei, out);
        cudaStreamWaitEvent(0, evJoin, 0);
    } else {
        cudaMemsetAsync(cnt_ptr, 0, NN * sizeof(int), 0);
        k_hist<<<(EE + 255) / 256, 256>>>(ei);
        k_scan_blocks<<<SCAN_NB, SCAN_T>>>();
        k_scan_add<<<(NN + 255) / 256, 256>>>();
        k_scatter<<<(ETOT + 255) / 256, 256>>>(ei);
        k_gemm_tc<<<(NN + 127) / 128, 256, GEMM_SMEM_BYTES>>>(x, W, att_src, att_dst);
        if (full) k_write_ei<<<(ETOT + 255) / 256, 256>>>(ei, out);
    }

    long long tc = (long long)NN * 32;
    k_aggregate<<<(int)((tc + 255) / 256), 256>>>(out, bias, full);

    if (forked) {
        cudaEventDestroy(evFork);
        cudaEventDestroy(evJoin);
        cudaStreamDestroy(s2);
    }
}

// round 14
// speedup vs baseline: 1.5827x; 1.1178x over previous
#include <cuda_runtime.h>
#include <cuda_fp16.h>
#include <cstdint>

// Problem constants (match reference)
#define NN   100000
#define DD   128
#define HH   8
#define CC   16
#define EE   800000
#define ETOT 900000          // E + N self-loops
#define NEG_SLOPE 0.2f
#define ALPHA_BASE (NN * DD + 2 * ETOT)

// scan config
#define SCAN_T   512
#define SCAN_IT  4
#define SCAN_PB  (SCAN_T * SCAN_IT)              // 2048
#define SCAN_NB  ((NN + SCAN_PB - 1) / SCAN_PB)  // 49

// Scratch (static __device__ globals; allocation is forbidden)
__device__ __align__(16) float g_h  [NN * DD];   // projected features (fp32)
__device__ __align__(16) float g_as [NN * HH];   // a_src
__device__ __align__(16) float g_ad [NN * HH];   // a_dst
__device__ int g_cnt [NN];
__device__ int g_inc [NN];
__device__ int g_bsum[SCAN_NB];
__device__ int g_off [NN + 1];
__device__ int g_cur [NN];
__device__ int g_esrc[ETOT];
__device__ int g_eid [ETOT];

// ===========================================================================
// fp16-split mma.sync GEMM:  h = x @ W  (hi*hi + hi*lo + lo*hi), fused att
// ===========================================================================
#define LDH 136
#define TILE_H (128 * LDH)
#define GEMM_SMEM_BYTES (4 * TILE_H * 2 + 256 * 4)

__device__ __forceinline__ void mma_f16(float* c, uint32_t a0, uint32_t a1,
                                        uint32_t a2, uint32_t a3,
                                        uint32_t b0, uint32_t b1) {
    asm volatile("mma.sync.aligned.m16n8k16.row.col.f32.f16.f16.f32 "
                 "{%0,%1,%2,%3}, {%4,%5,%6,%7}, {%8,%9}, {%0,%1,%2,%3};"
                 : "+f"(c[0]), "+f"(c[1]), "+f"(c[2]), "+f"(c[3])
                 : "r"(a0), "r"(a1), "r"(a2), "r"(a3), "r"(b0), "r"(b1));
}

__global__ __launch_bounds__(256, 1)
void k_gemm_tc(const float* __restrict__ x, const float* __restrict__ W,
               const float* __restrict__ att_src, const float* __restrict__ att_dst) {
    extern __shared__ char smraw[];
    __half* As_hi = (__half*)smraw;
    __half* As_lo = As_hi + TILE_H;
    __half* Bs_hi = As_lo + TILE_H;
    __half* Bs_lo = Bs_hi + TILE_H;
    float*  Satt  = (float*)(Bs_lo + TILE_H);

    const int tid  = threadIdx.x;
    const int wid  = tid >> 5;
    const int lane = tid & 31;
    const int gid  = lane >> 2;
    const int tig  = lane & 3;
    const int bm   = blockIdx.x * 128;
    const int wr   = wid & 1;
    const int wc   = wid >> 1;
    const int mbase = wr * 64;
    const int nbase = wc * 32;

    #pragma unroll
    for (int i = 0; i < 16; i++) {
        int f = tid + i * 256;
        int row = f >> 5, c4 = f & 31;
        float4 v = make_float4(0.f, 0.f, 0.f, 0.f);
        if (bm + row < NN) v = *(const float4*)&x[(size_t)(bm + row) * DD + c4 * 4];
        float vv[4] = { v.x, v.y, v.z, v.w };
        #pragma unroll
        for (int j = 0; j < 4; j++) {
            __half hi = __float2half_rn(vv[j]);
            __half lo = __float2half_rn(vv[j] - __half2float(hi));
            As_hi[row * LDH + c4 * 4 + j] = hi;
            As_lo[row * LDH + c4 * 4 + j] = lo;
        }
    }
    #pragma unroll
    for (int i = 0; i < 16; i++) {
        int f = tid + i * 256;
        int k = f >> 5, n4 = f & 31;
        float4 v = *(const float4*)&W[(size_t)k * DD + n4 * 4];
        float vv[4] = { v.x, v.y, v.z, v.w };
        #pragma unroll
        for (int j = 0; j < 4; j++) {
            __half hi = __float2half_rn(vv[j]);
            __half lo = __float2half_rn(vv[j] - __half2float(hi));
            Bs_hi[(n4 * 4 + j) * LDH + k] = hi;
            Bs_lo[(n4 * 4 + j) * LDH + k] = lo;
        }
    }
    if (tid < 128) {
        Satt[tid]       = att_src[tid];
        Satt[128 + tid] = att_dst[tid];
    }
    __syncthreads();

    float acc[4][4][4];
    #pragma unroll
    for (int mt = 0; mt < 4; mt++)
        #pragma unroll
        for (int nt = 0; nt < 4; nt++)
            #pragma unroll
            for (int j = 0; j < 4; j++) acc[mt][nt][j] = 0.f;

    #pragma unroll
    for (int kt = 0; kt < 8; kt++) {
        const int kc = kt * 16 + tig * 2;
        uint32_t ah[4][4], al[4][4];
        #pragma unroll
        for (int mt = 0; mt < 4; mt++) {
            int r0 = (mbase + mt * 16 + gid) * LDH;
            int r1 = r0 + 8 * LDH;
            ah[mt][0] = *(const uint32_t*)&As_hi[r0 + kc];
            ah[mt][1] = *(const uint32_t*)&As_hi[r1 + kc];
            ah[mt][2] = *(const uint32_t*)&As_hi[r0 + kc + 8];
            ah[mt][3] = *(const uint32_t*)&As_hi[r1 + kc + 8];
            al[mt][0] = *(const uint32_t*)&As_lo[r0 + kc];
            al[mt][1] = *(const uint32_t*)&As_lo[r1 + kc];
            al[mt][2] = *(const uint32_t*)&As_lo[r0 + kc + 8];
            al[mt][3] = *(const uint32_t*)&As_lo[r1 + kc + 8];
        }
        uint32_t bh[4][2], bl[4][2];
        #pragma unroll
        for (int nt = 0; nt < 4; nt++) {
            int nr = (nbase + nt * 8 + gid) * LDH;
            bh[nt][0] = *(const uint32_t*)&Bs_hi[nr + kc];
            bh[nt][1] = *(const uint32_t*)&Bs_hi[nr + kc + 8];
            bl[nt][0] = *(const uint32_t*)&Bs_lo[nr + kc];
            bl[nt][1] = *(const uint32_t*)&Bs_lo[nr + kc + 8];
        }
        #pragma unroll
        for (int mt = 0; mt < 4; mt++)
            #pragma unroll
            for (int nt = 0; nt < 4; nt++) {
                mma_f16(acc[mt][nt], ah[mt][0], ah[mt][1], ah[mt][2], ah[mt][3],
                        bh[nt][0], bh[nt][1]);
                mma_f16(acc[mt][nt], ah[mt][0], ah[mt][1], ah[mt][2], ah[mt][3],
                        bl[nt][0], bl[nt][1]);
                mma_f16(acc[mt][nt], al[mt][0], al[mt][1], al[mt][2], al[mt][3],
                        bh[nt][0], bh[nt][1]);
            }
    }

    #pragma unroll
    for (int mt = 0; mt < 4; mt++) {
        #pragma unroll
        for (int half = 0; half < 2; half++) {
            const int grow = bm + mbase + mt * 16 + half * 8 + gid;
            const bool ok  = (grow < NN);
            float sacc[2] = {0.f, 0.f}, dacc[2] = {0.f, 0.f};
            #pragma unroll
            for (int nt = 0; nt < 4; nt++) {
                float v0 = acc[mt][nt][half * 2];
                float v1 = acc[mt][nt][half * 2 + 1];
                int c0 = nbase + nt * 8 + tig * 2;
                if (ok) {
                    float2 st = make_float2(v0, v1);
                    *(float2*)&g_h[(size_t)grow * DD + c0] = st;
                }
                int hl = nt >> 1;
                sacc[hl] = fmaf(v0, Satt[c0], fmaf(v1, Satt[c0 + 1], sacc[hl]));
                dacc[hl] = fmaf(v0, Satt[128 + c0], fmaf(v1, Satt[128 + c0 + 1], dacc[hl]));
            }
            #pragma unroll
            for (int o = 1; o <= 2; o <<= 1) {
                #pragma unroll
                for (int hl = 0; hl < 2; hl++) {
                    sacc[hl] += __shfl_xor_sync(0xffffffffu, sacc[hl], o);
                    dacc[hl] += __shfl_xor_sync(0xffffffffu, dacc[hl], o);
                }
            }
            if (ok && tig == 0) {
                #pragma unroll
                for (int hl = 0; hl < 2; hl++) {
                    g_as[grow * HH + wc * 2 + hl] = sacc[hl];
                    g_ad[grow * HH + wc * 2 + hl] = dacc[hl];
                }
            }
        }
    }
}

// ---------------------------------------------------------------------------
// CSR build  (g_cnt memset to 0 host-side; self-loop +1 folded into the scan)
// ---------------------------------------------------------------------------
__global__ void k_hist(const int* __restrict__ ei) {
    int e = blockIdx.x * blockDim.x + threadIdx.x;
    if (e < EE) atomicAdd(&g_cnt[ei[EE + e]], 1);
}

__global__ void k_scan_blocks() {
    __shared__ int ssum[SCAN_T];
    int b = blockIdx.x, t = threadIdx.x;
    int base = b * SCAN_PB + t * SCAN_IT;
    int v[SCAN_IT];
    int tot = 0;
    #pragma unroll
    for (int k = 0; k < SCAN_IT; k++) {
        v[k] = (base + k < NN) ? (g_cnt[base + k] + 1) : 0;   // +1 self-loop
        tot += v[k];
    }
    ssum[t] = tot;
    __syncthreads();
    for (int o = 1; o < SCAN_T; o <<= 1) {
        int x = (t >= o) ? ssum[t - o] : 0;
        __syncthreads();
        ssum[t] += x;
        __syncthreads();
    }
    int run = ssum[t] - tot;
    #pragma unroll
    for (int k = 0; k < SCAN_IT; k++) {
        run += v[k];
        if (base + k < NN) g_inc[base + k] = run;
    }
    if (t == SCAN_T - 1) g_bsum[b] = ssum[SCAN_T - 1];
}

__global__ void k_scan_add() {
    __shared__ int sb[SCAN_NB];
    int t = threadIdx.x;
    if (t < SCAN_NB) sb[t] = g_bsum[t];
    __syncthreads();
    int i = blockIdx.x * blockDim.x + t;
    if (i >= NN) return;
    int mb = i / SCAN_PB;
    int ex = 0;
    for (int j = 0; j < mb; j++) ex += sb[j];
    int excl = g_inc[i] - (g_cnt[i] + 1) + ex;
    g_off[i] = excl;
    g_cur[i] = excl;
    if (i == 0) g_off[NN] = ETOT;
}

__global__ void k_scatter(const int* __restrict__ ei) {
    int e = blockIdx.x * blockDim.x + threadIdx.x;
    if (e >= ETOT) return;
    int s, d;
    if (e < EE) { s = ei[e]; d = ei[EE + e]; }
    else        { s = e - EE; d = s; }
    int pos = atomicAdd(&g_cur[d], 1);
    g_esrc[pos] = s;
    g_eid[pos]  = e;
}

__global__ void k_write_ei(const int* __restrict__ ei, float* __restrict__ out) {
    int e = blockIdx.x * blockDim.x + threadIdx.x;
    if (e >= ETOT) return;
    int s, d;
    if (e < EE) { s = ei[e]; d = ei[EE + e]; }
    else        { s = e - EE; d = s; }
    out[NN * DD + e]        = (float)s;
    out[NN * DD + ETOT + e] = (float)d;
}

// ---------------------------------------------------------------------------
// fused softmax + aggregation: one warp per destination node
// fast path: no max-subtraction (logits bounded), unnormalized ex in smem,
// one reciprocal per (warp, head) instead of per-lane divides.
// ---------------------------------------------------------------------------
__global__ __launch_bounds__(256)
void k_aggregate(float* __restrict__ out, const float* __restrict__ bias, int full) {
    __shared__ __align__(16) float s_ex [8][32][8];  // unnormalized exp / mx,den
    __shared__ int   s_src[8][32];
    __shared__ __align__(16) float s_inv[8][8];      // per-warp per-head 1/den

    const int warp = (blockIdx.x * blockDim.x + threadIdx.x) >> 5;
    const int lane = threadIdx.x & 31;
    const int w    = threadIdx.x >> 5;
    if (warp >= NN) return;
    const int n   = warp;
    const int beg = g_off[n];                 // scalar loads: no alignment hazard
    const int deg = g_off[n + 1] - beg;
    const int hd  = lane >> 2;
    const int q   = lane & 3;

    float4 ad0 = *(const float4*)&g_ad[n * HH];
    float4 ad1 = *(const float4*)&g_ad[n * HH + 4];
    const float adv[8] = { ad0.x, ad0.y, ad0.z, ad0.w, ad1.x, ad1.y, ad1.z, ad1.w };

    if (deg <= 32) {
        // ---- fast path: lane j owns edge j ----
        float ex[8];
        int   s = 0, eid = 0;
        if (lane < deg) {
            s   = g_esrc[beg + lane];
            eid = g_eid[beg + lane];
            float4 s0 = *(const float4*)&g_as[s * HH];
            float4 s1 = *(const float4*)&g_as[s * HH + 4];
            float t[8] = { s0.x + adv[0], s0.y + adv[1], s0.z + adv[2], s0.w + adv[3],
                           s1.x + adv[4], s1.y + adv[5], s1.z + adv[6], s1.w + adv[7] };
            #pragma unroll
            for (int r = 0; r < 8; r++) {
                float v = (t[r] > 0.f) ? t[r] : NEG_SLOPE * t[r];
                ex[r] = __expf(v);                 // logits bounded ~|6|: safe w/o max
            }
            s_src[w][lane] = s;
            #pragma unroll
            for (int r = 0; r < 8; r++) s_ex[w][lane][r] = ex[r];
        } else {
            #pragma unroll
            for (int r = 0; r < 8; r++) ex[r] = 0.f;
        }

        float den[8];
        #pragma unroll
        for (int r = 0; r < 8; r++) den[r] = ex[r];
        #pragma unroll
        for (int o = 16; o > 0; o >>= 1)
            #pragma unroll
            for (int r = 0; r < 8; r++)
                den[r] += __shfl_xor_sync(0xffffffffu, den[r], o);

        if (lane < 8) s_inv[w][lane] = 1.0f / (den[lane] + 1e-16f);
        __syncwarp();

        if (full && lane < deg) {
            float4 i0 = *(const float4*)&s_inv[w][0];
            float4 i1 = *(const float4*)&s_inv[w][4];
            float* ap = &out[ALPHA_BASE + (size_t)eid * HH];
            *(float4*)ap       = make_float4(ex[0] * i0.x, ex[1] * i0.y,
                                             ex[2] * i0.z, ex[3] * i0.w);
            *(float4*)(ap + 4) = make_float4(ex[4] * i1.x, ex[5] * i1.y,
                                             ex[6] * i1.z, ex[7] * i1.w);
        }

        const float inv_h = s_inv[w][hd];
        float4 acc = make_float4(0.f, 0.f, 0.f, 0.f);
        #pragma unroll 4
        for (int j = 0; j < deg; j++) {
            int   sj    = s_src[w][j];
            float alpha = s_ex[w][j][hd] * inv_h;
            float4 hv = __ldg((const float4*)&g_h[(size_t)sj * DD + hd * CC + q * 4]);
            acc.x = fmaf(alpha, hv.x, acc.x);
            acc.y = fmaf(alpha, hv.y, acc.y);
            acc.z = fmaf(alpha, hv.z, acc.z);
            acc.w = fmaf(alpha, hv.w, acc.w);
        }
        float4 b = *(const float4*)&bias[lane * 4];
        acc.x += b.x; acc.y += b.y; acc.z += b.z; acc.w += b.w;
        *(float4*)&out[(size_t)n * DD + lane * 4] = acc;
        return;
    }

    // ---- fallback: deg > 32 (rare) — keeps max for robustness ----
    float mx[8];
    #pragma unroll
    for (int r = 0; r < 8; r++) mx[r] = __int_as_float(0xFF800000);
    for (int j = lane; j < deg; j += 32) {
        int s = g_esrc[beg + j];
        float4 s0 = *(const float4*)&g_as[s * HH];
        float4 s1 = *(const float4*)&g_as[s * HH + 4];
        float l[8] = { s0.x + adv[0], s0.y + adv[1], s0.z + adv[2], s0.w + adv[3],
                       s1.x + adv[4], s1.y + adv[5], s1.z + adv[6], s1.w + adv[7] };
        #pragma unroll
        for (int r = 0; r < 8; r++) {
            float v = (l[r] > 0.f) ? l[r] : NEG_SLOPE * l[r];
            mx[r] = fmaxf(mx[r], v);
        }
    }
    #pragma unroll
    for (int o = 16; o > 0; o >>= 1)
        #pragma unroll
        for (int r = 0; r < 8; r++)
            mx[r] = fmaxf(mx[r], __shfl_xor_sync(0xffffffffu, mx[r], o));

    float den[8];
    #pragma unroll
    for (int r = 0; r < 8; r++) den[r] = 0.f;
    for (int j = lane; j < deg; j += 32) {
        int s = g_esrc[beg + j];
        float4 s0 = *(const float4*)&g_as[s * HH];
        float4 s1 = *(const float4*)&g_as[s * HH + 4];
        float l[8] = { s0.x + adv[0], s0.y + adv[1], s0.z + adv[2], s0.w + adv[3],
                       s1.x + adv[4], s1.y + adv[5], s1.z + adv[6], s1.w + adv[7] };
        #pragma unroll
        for (int r = 0; r < 8; r++) {
            float v = (l[r] > 0.f) ? l[r] : NEG_SLOPE * l[r];
            den[r] += __expf(v - mx[r]);
        }
    }
    #pragma unroll
    for (int o = 16; o > 0; o >>= 1)
        #pragma unroll
        for (int r = 0; r < 8; r++)
            den[r] += __shfl_xor_sync(0xffffffffu, den[r], o);

    if (lane < 8) { s_ex[w][0][lane] = mx[lane]; s_ex[w][1][lane] = den[lane]; }
    __syncwarp();
    const float m_h   = s_ex[w][0][hd];
    const float den_h = s_ex[w][1][hd] + 1e-16f;
    const float adh   = adv[hd];

    float4 acc = make_float4(0.f, 0.f, 0.f, 0.f);
    for (int j = 0; j < deg; j++) {
        int s = g_esrc[beg + j];
        float l = g_as[s * HH + hd] + adh;
        l = (l > 0.f) ? l : NEG_SLOPE * l;
        float alpha = __expf(l - m_h) / den_h;
        if (full && q == 0) {
            int eid = g_eid[beg + j];
            out[ALPHA_BASE + (size_t)eid * HH + hd] = alpha;
        }
        float4 hv = __ldg((const float4*)&g_h[(size_t)s * DD + hd * CC + q * 4]);
        acc.x = fmaf(alpha, hv.x, acc.x);
        acc.y = fmaf(alpha, hv.y, acc.y);
        acc.z = fmaf(alpha, hv.z, acc.z);
        acc.w = fmaf(alpha, hv.w, acc.w);
    }
    float4 b = *(const float4*)&bias[lane * 4];
    acc.x += b.x; acc.y += b.y; acc.z += b.z; acc.w += b.w;
    *(float4*)&out[(size_t)n * DD + lane * 4] = acc;
}

// ---------------------------------------------------------------------------
extern "C" void kernel_launch(void* const* d_in, const int* in_sizes, int n_in,
                              void* d_out, int out_size) {
    const float* x       = (const float*)d_in[0];
    const int*   ei      = (const int*)d_in[1];    // int32 (JAX x64 disabled)
    const float* W       = (const float*)d_in[2];
    const float* att_src = (const float*)d_in[3];
    const float* att_dst = (const float*)d_in[4];
    const float* bias    = (const float*)d_in[5];
    float* out = (float*)d_out;

    const int full = (out_size > NN * DD) ? 1 : 0;

    cudaFuncSetAttribute(k_gemm_tc, cudaFuncAttributeMaxDynamicSharedMemorySize,
                         GEMM_SMEM_BYTES);

    void* cnt_ptr = nullptr;
    cudaGetSymbolAddress(&cnt_ptr, g_cnt);

    cudaStream_t s2;
    cudaEvent_t evFork, evJoin;
    bool forked = (cudaStreamCreateWithFlags(&s2, cudaStreamNonBlocking) == cudaSuccess);
    if (forked) {
        cudaEventCreateWithFlags(&evFork, cudaEventDisableTiming);
        cudaEventCreateWithFlags(&evJoin, cudaEventDisableTiming);
    }

    if (forked) {
        cudaEventRecord(evFork, 0);
        cudaStreamWaitEvent(s2, evFork, 0);
        cudaMemsetAsync(cnt_ptr, 0, NN * sizeof(int), s2);
        k_hist<<<(EE + 255) / 256, 256, 0, s2>>>(ei);
        k_scan_blocks<<<SCAN_NB, SCAN_T, 0, s2>>>();
        k_scan_add<<<(NN + 255) / 256, 256, 0, s2>>>();
        k_scatter<<<(ETOT + 255) / 256, 256, 0, s2>>>(ei);
        cudaEventRecord(evJoin, s2);

        k_gemm_tc<<<(NN + 127) / 128, 256, GEMM_SMEM_BYTES>>>(x, W, att_src, att_dst);
        if (full) k_write_ei<<<(ETOT + 255) / 256, 256>>>(ei, out);
        cudaStreamWaitEvent(0, evJoin, 0);
    } else {
        cudaMemsetAsync(cnt_ptr, 0, NN * sizeof(int), 0);
        k_hist<<<(EE + 255) / 256, 256>>>(ei);
        k_scan_blocks<<<SCAN_NB, SCAN_T>>>();
        k_scan_add<<<(NN + 255) / 256, 256>>>();
        k_scatter<<<(ETOT + 255) / 256, 256>>>(ei);
        k_gemm_tc<<<(NN + 127) / 128, 256, GEMM_SMEM_BYTES>>>(x, W, att_src, att_dst);
        if (full) k_write_ei<<<(ETOT + 255) / 256, 256>>>(ei, out);
    }

    long long tc = (long long)NN * 32;
    k_aggregate<<<(int)((tc + 255) / 256), 256>>>(out, bias, full);

    if (forked) {
        cudaEventDestroy(evFork);
        cudaEventDestroy(evJoin);
        cudaStreamDestroy(s2);
    }
}